// round 1
// baseline (speedup 1.0000x reference)
#include <cuda_runtime.h>
#include <math.h>

// Problem shape (fixed by setup_inputs):
//   B = 8192, I = 512, H = 1024, N = 4*H = 4096, Ktot = I + H = 1536
// gates[B, 4, H] = x@Wi + h@Wh + bh ; per-gate LayerNorm over H; LSTM math.
// Output: d_out = [h_new (B*H) | c_new (B*H)]  (float32)

#define B_DIM 8192
#define I_DIM 512
#define H_DIM 1024
#define N_DIM 4096   // 4*H

// Scratch for the gates matrix: 8192 * 4096 floats = 128 MB (device global = allowed)
__device__ float g_gates[(size_t)B_DIM * N_DIM];

// ---------------------------------------------------------------------------
// Kernel 1: fused SGEMM  gates = x @ Wi + h @ Wh + bh
//   Tile: BM=128, BN=128, BK=8 ; 256 threads ; 8x8 per-thread register tile.
// ---------------------------------------------------------------------------
#define BM 128
#define BN 128
#define BK 8
#define TM 8
#define TN 8

__global__ __launch_bounds__(256, 2)
void gates_gemm_kernel(const float* __restrict__ X,   // [B, I]
                       const float* __restrict__ Hm,  // [B, H]
                       const float* __restrict__ Wi,  // [I, N]
                       const float* __restrict__ Wh,  // [H, N]
                       const float* __restrict__ bh,  // [N]
                       float* __restrict__ out)       // [B, N]
{
    __shared__ float As[BK][BM];
    __shared__ float Bs[BK][BN];

    const int tid = threadIdx.x;
    const int block_row = blockIdx.y * BM;
    const int block_col = blockIdx.x * BN;

    // loader mapping
    const int a_row  = tid >> 1;          // 0..127
    const int a_col4 = (tid & 1) * 4;     // 0 or 4
    const int b_row  = tid >> 5;          // 0..7
    const int b_col4 = (tid & 31) * 4;    // 0..124

    // compute mapping: 16 x 16 thread grid, each 8x8
    const int ty = tid >> 4;
    const int tx = tid & 15;
    const int m0 = ty * TM;
    const int n0 = tx * TN;

    float acc[TM][TN];
#pragma unroll
    for (int i = 0; i < TM; ++i)
#pragma unroll
        for (int j = 0; j < TN; ++j) acc[i][j] = 0.0f;

#pragma unroll 1
    for (int phase = 0; phase < 2; ++phase) {
        const float* A = phase ? Hm : X;
        const float* W = phase ? Wh : Wi;
        const int K = phase ? H_DIM : I_DIM;

        const float* a_ptr = A + (size_t)(block_row + a_row) * K + a_col4;
        const float* w_ptr = W + (size_t)b_row * N_DIM + block_col + b_col4;

#pragma unroll 1
        for (int k0 = 0; k0 < K; k0 += BK) {
            // stage A tile (transposed) and W tile
            float4 av = *(const float4*)(a_ptr + k0);
            As[a_col4 + 0][a_row] = av.x;
            As[a_col4 + 1][a_row] = av.y;
            As[a_col4 + 2][a_row] = av.z;
            As[a_col4 + 3][a_row] = av.w;
            float4 wv = *(const float4*)(w_ptr + (size_t)k0 * N_DIM);
            *(float4*)&Bs[b_row][b_col4] = wv;
            __syncthreads();

#pragma unroll
            for (int kk = 0; kk < BK; ++kk) {
                float a_reg[TM], b_reg[TN];
                float4 a0 = *(const float4*)&As[kk][m0];
                float4 a1 = *(const float4*)&As[kk][m0 + 4];
                a_reg[0]=a0.x; a_reg[1]=a0.y; a_reg[2]=a0.z; a_reg[3]=a0.w;
                a_reg[4]=a1.x; a_reg[5]=a1.y; a_reg[6]=a1.z; a_reg[7]=a1.w;
                float4 b0 = *(const float4*)&Bs[kk][n0];
                float4 b1 = *(const float4*)&Bs[kk][n0 + 4];
                b_reg[0]=b0.x; b_reg[1]=b0.y; b_reg[2]=b0.z; b_reg[3]=b0.w;
                b_reg[4]=b1.x; b_reg[5]=b1.y; b_reg[6]=b1.z; b_reg[7]=b1.w;
#pragma unroll
                for (int i = 0; i < TM; ++i)
#pragma unroll
                    for (int j = 0; j < TN; ++j)
                        acc[i][j] = fmaf(a_reg[i], b_reg[j], acc[i][j]);
            }
            __syncthreads();
        }
    }

    // epilogue: + bias, store
#pragma unroll
    for (int i = 0; i < TM; ++i) {
        const size_t row = (size_t)(block_row + m0 + i);
#pragma unroll
        for (int j = 0; j < TN; j += 4) {
            const int col = block_col + n0 + j;
            float4 bv = *(const float4*)&bh[col];
            float4 o;
            o.x = acc[i][j + 0] + bv.x;
            o.y = acc[i][j + 1] + bv.y;
            o.z = acc[i][j + 2] + bv.z;
            o.w = acc[i][j + 3] + bv.w;
            *(float4*)&out[row * N_DIM + col] = o;
        }
    }
}

// ---------------------------------------------------------------------------
// Kernel 2: per-row LayerNorm (per gate) + LSTM elementwise
//   One block (128 threads = 4 warps) per batch row; warp w handles gate w.
// ---------------------------------------------------------------------------
__device__ __forceinline__ float sigmoidf_(float x) {
    return 1.0f / (1.0f + expf(-x));
}

__global__ __launch_bounds__(128)
void ln_lstm_kernel(const float* __restrict__ gates,  // [B, 4, H]
                    const float* __restrict__ c,      // [B, H]
                    const float* __restrict__ gamma,  // [4, H]
                    const float* __restrict__ beta,   // [4, H]
                    float* __restrict__ h_new,        // [B, H]
                    float* __restrict__ c_new)        // [B, H]
{
    const int b    = blockIdx.x;
    const int wid  = threadIdx.x >> 5;   // gate index 0..3
    const int lane = threadIdx.x & 31;

    __shared__ float sh[4][H_DIM];

    const float* row = gates + (size_t)b * N_DIM + wid * H_DIM;

    // Each lane loads 8 float4 = 32 floats (H=1024 = 32 lanes * 32)
    float4 v[8];
    float sum = 0.0f, sumsq = 0.0f;
#pragma unroll
    for (int i = 0; i < 8; ++i) {
        v[i] = *(const float4*)&row[(lane + 32 * i) * 4];
        sum   += v[i].x + v[i].y + v[i].z + v[i].w;
        sumsq += v[i].x * v[i].x + v[i].y * v[i].y
               + v[i].z * v[i].z + v[i].w * v[i].w;
    }
#pragma unroll
    for (int off = 16; off > 0; off >>= 1) {
        sum   += __shfl_xor_sync(0xffffffffu, sum,   off);
        sumsq += __shfl_xor_sync(0xffffffffu, sumsq, off);
    }
    const float inv_n = 1.0f / (float)H_DIM;
    const float mean = sum * inv_n;
    const float var  = fmaxf(sumsq * inv_n - mean * mean, 0.0f);
    const float rstd = rsqrtf(var + 1e-5f);

    const float* gam = gamma + wid * H_DIM;
    const float* bet = beta  + wid * H_DIM;
#pragma unroll
    for (int i = 0; i < 8; ++i) {
        const int j = (lane + 32 * i) * 4;
        float4 gv = *(const float4*)&gam[j];
        float4 bv = *(const float4*)&bet[j];
        float4 y;
        y.x = (v[i].x - mean) * rstd * gv.x + bv.x;
        y.y = (v[i].y - mean) * rstd * gv.y + bv.y;
        y.z = (v[i].z - mean) * rstd * gv.z + bv.z;
        y.w = (v[i].w - mean) * rstd * gv.w + bv.w;
        *(float4*)&sh[wid][j] = y;
    }
    __syncthreads();

    // 128 threads x 2 float4 = 1024 elements
    const size_t base = (size_t)b * H_DIM;
#pragma unroll
    for (int ii = 0; ii < 2; ++ii) {
        const int j = (threadIdx.x + 128 * ii) * 4;
        float4 ig = *(const float4*)&sh[0][j];
        float4 fg = *(const float4*)&sh[1][j];
        float4 gg = *(const float4*)&sh[2][j];
        float4 og = *(const float4*)&sh[3][j];
        float4 cv = *(const float4*)&c[base + j];

        float4 cn, hn;
        cn.x = sigmoidf_(fg.x) * cv.x + sigmoidf_(ig.x) * tanhf(gg.x);
        cn.y = sigmoidf_(fg.y) * cv.y + sigmoidf_(ig.y) * tanhf(gg.y);
        cn.z = sigmoidf_(fg.z) * cv.z + sigmoidf_(ig.z) * tanhf(gg.z);
        cn.w = sigmoidf_(fg.w) * cv.w + sigmoidf_(ig.w) * tanhf(gg.w);
        hn.x = sigmoidf_(og.x) * tanhf(cn.x);
        hn.y = sigmoidf_(og.y) * tanhf(cn.y);
        hn.z = sigmoidf_(og.z) * tanhf(cn.z);
        hn.w = sigmoidf_(og.w) * tanhf(cn.w);

        *(float4*)&c_new[base + j] = cn;
        *(float4*)&h_new[base + j] = hn;
    }
}

// ---------------------------------------------------------------------------
// Launcher
// ---------------------------------------------------------------------------
extern "C" void kernel_launch(void* const* d_in, const int* in_sizes, int n_in,
                              void* d_out, int out_size)
{
    const float* x     = (const float*)d_in[0];  // [B, I]
    const float* h     = (const float*)d_in[1];  // [B, H]
    const float* c     = (const float*)d_in[2];  // [B, H]
    const float* Wi    = (const float*)d_in[3];  // [I, 4H]
    const float* Wh    = (const float*)d_in[4];  // [H, 4H]
    const float* bh    = (const float*)d_in[5];  // [4H]
    const float* gamma = (const float*)d_in[6];  // [4, H]
    const float* beta  = (const float*)d_in[7];  // [4, H]

    float* out   = (float*)d_out;
    float* h_new = out;                                  // [B, H]
    float* c_new = out + (size_t)B_DIM * H_DIM;          // [B, H]

    float* gates;
    cudaGetSymbolAddress((void**)&gates, g_gates);

    dim3 gemm_grid(N_DIM / BN, B_DIM / BM);   // (32, 64)
    gates_gemm_kernel<<<gemm_grid, 256>>>(x, h, Wi, Wh, bh, gates);

    ln_lstm_kernel<<<B_DIM, 128>>>(gates, c, gamma, beta, h_new, c_new);
}

// round 3
// speedup vs baseline: 2.2135x; 2.2135x over previous
#include <cuda_runtime.h>
#include <cuda_bf16.h>
#include <math.h>
#include <stdint.h>

// ---------------------------------------------------------------------------
// Shapes: B=8192, I=512, H=1024, N=4096, K=1536, K_eff=3*1536=4608
// gates = x@Wi + h@Wh (bias folded into LN); per-gate LayerNorm; LSTM math.
// GEMM: bf16 split (3 first-order terms) via mma.sync.m16n8k16, fp32 accum.
// ---------------------------------------------------------------------------
#define B_DIM 8192
#define I_DIM 512
#define H_DIM 1024
#define N_DIM 4096
#define K_RAW 1536
#define K_EFF 4608

__device__ float g_gates[(size_t)B_DIM * N_DIM];                        // 128 MB
__device__ __align__(1024) __nv_bfloat16 g_Acat[(size_t)B_DIM * K_EFF]; // 75 MB
__device__ __align__(1024) __nv_bfloat16 g_Wcat[(size_t)N_DIM * K_EFF]; // 38 MB

// ------------------------------ PTX helpers --------------------------------
__device__ __forceinline__ uint32_t smem_u32(const void* p) {
    uint32_t a;
    asm("{ .reg .u64 t; cvta.to.shared.u64 t, %1; cvt.u32.u64 %0, t; }"
        : "=r"(a) : "l"(p));
    return a;
}

__device__ __forceinline__ void cp16(uint32_t dst, const void* src) {
    asm volatile("cp.async.cg.shared.global [%0], [%1], 16;"
                 :: "r"(dst), "l"(src) : "memory");
}
#define CP_COMMIT() asm volatile("cp.async.commit_group;" ::: "memory")
#define CP_WAIT2()  asm volatile("cp.async.wait_group 2;"  ::: "memory")

#define LDSM_X4(r, addr)                                                      \
    asm volatile("ldmatrix.sync.aligned.m8n8.x4.shared.b16 {%0,%1,%2,%3}, [%4];" \
        : "=r"((r)[0]), "=r"((r)[1]), "=r"((r)[2]), "=r"((r)[3]) : "r"(addr))

#define MMA16816(d, a, b0, b1)                                                \
    asm volatile("mma.sync.aligned.m16n8k16.row.col.f32.bf16.bf16.f32 "       \
        "{%0,%1,%2,%3}, {%4,%5,%6,%7}, {%8,%9}, {%0,%1,%2,%3};"               \
        : "+f"((d)[0]), "+f"((d)[1]), "+f"((d)[2]), "+f"((d)[3])              \
        : "r"((a)[0]), "r"((a)[1]), "r"((a)[2]), "r"((a)[3]),                 \
          "r"(b0), "r"(b1))

// ---------------------------------------------------------------------------
// Pack kernels: split-bf16 operands.
//   A_cat[b][k'] = [hi | lo | hi] of (x|h)[b]
//   W_cat[n][k'] = [hi | hi | lo] of W[.][n]  (K-major, transposed)
// ---------------------------------------------------------------------------
__global__ __launch_bounds__(256)
void pack_a_kernel(const float* __restrict__ x, const float* __restrict__ h) {
    const int b = blockIdx.y;
    const int k = blockIdx.x * 256 + threadIdx.x;
    float v = (k < I_DIM) ? x[(size_t)b * I_DIM + k]
                          : h[(size_t)b * H_DIM + (k - I_DIM)];
    __nv_bfloat16 hi = __float2bfloat16(v);
    __nv_bfloat16 lo = __float2bfloat16(v - __bfloat162float(hi));
    const size_t base = (size_t)b * K_EFF;
    g_Acat[base + k]             = hi;
    g_Acat[base + K_RAW + k]     = lo;
    g_Acat[base + 2 * K_RAW + k] = hi;
}

__global__ __launch_bounds__(256)
void pack_w_kernel(const float* __restrict__ Wi, const float* __restrict__ Wh) {
    __shared__ float t[32][33];
    const int k0 = blockIdx.x * 32;
    const int n0 = blockIdx.y * 32;
    const int tx = threadIdx.x, ty = threadIdx.y; // 32 x 8
#pragma unroll
    for (int i = 0; i < 4; ++i) {
        const int k = k0 + ty + i * 8;
        const int n = n0 + tx;
        float v = (k < I_DIM) ? Wi[(size_t)k * N_DIM + n]
                              : Wh[(size_t)(k - I_DIM) * N_DIM + n];
        t[ty + i * 8][tx] = v;
    }
    __syncthreads();
#pragma unroll
    for (int i = 0; i < 4; ++i) {
        const int n = n0 + ty + i * 8;
        const int k = k0 + tx;
        float v = t[tx][ty + i * 8];
        __nv_bfloat16 hi = __float2bfloat16(v);
        __nv_bfloat16 lo = __float2bfloat16(v - __bfloat162float(hi));
        const size_t base = (size_t)n * K_EFF;
        g_Wcat[base + k]             = hi;
        g_Wcat[base + K_RAW + k]     = hi;
        g_Wcat[base + 2 * K_RAW + k] = lo;
    }
}

// ---------------------------------------------------------------------------
// bf16 TN GEMM: gates[M,N] = A_cat[M,K] @ W_cat[N,K]^T
//   CTA 128x128x64, 256 thr, 8 warps (2m x 4n), warp tile 64x32.
//   4-stage cp.async pipeline, XOR-swizzled smem, ldmatrix + mma.m16n8k16.
// ---------------------------------------------------------------------------
#define STAGES 4
#define BK 64
#define TILE_M 128
#define TILE_N 128
#define NK (K_EFF / BK)              // 72
#define STAGE_BYTES 32768            // A 16KB + B 16KB
#define SMEM_BYTES (STAGES * STAGE_BYTES)

__device__ __forceinline__ void issue_stage(uint32_t sbase, int s,
                                            const __nv_bfloat16* A,
                                            const __nv_bfloat16* W,
                                            int m0, int n0, int k0, int tid) {
    const uint32_t sA = sbase + s * STAGE_BYTES;
    const uint32_t sB = sA + 16384;
#pragma unroll
    for (int i = 0; i < 4; ++i) {
        const int idx = tid + 256 * i;          // 0..1023
        const int row = idx >> 3;               // 0..127
        const int c   = idx & 7;                // 16B chunk
        const uint32_t dst_off = row * 128 + ((c ^ (row & 7)) << 4);
        cp16(sA + dst_off, A + (size_t)(m0 + row) * K_EFF + k0 + c * 8);
        cp16(sB + dst_off, W + (size_t)(n0 + row) * K_EFF + k0 + c * 8);
    }
}

__global__ void __launch_bounds__(256, 1)
gemm_mma_kernel(const __nv_bfloat16* __restrict__ A,
                const __nv_bfloat16* __restrict__ W,
                float* __restrict__ out) {
    extern __shared__ char smem[];
    const uint32_t sbase = smem_u32(smem);

    const int tid  = threadIdx.x;
    const int wid  = tid >> 5;
    const int lane = tid & 31;
    const int warp_m = wid >> 2;     // 0..1  -> 64 rows
    const int warp_n = wid & 3;      // 0..3  -> 32 cols
    const int m0 = blockIdx.y * TILE_M;
    const int n0 = blockIdx.x * TILE_N;

    // ldmatrix lane addressing (within a 16x16 tile, 2 chunk-halves)
    const int lrow  = (lane & 7) + ((lane >> 3) & 1) * 8;  // 0..15
    const int lhalf = lane >> 4;                           // 0 or 1 (k chunk)

    float acc[4][4][4];
#pragma unroll
    for (int i = 0; i < 4; ++i)
#pragma unroll
        for (int j = 0; j < 4; ++j)
#pragma unroll
            for (int e = 0; e < 4; ++e) acc[i][j][e] = 0.0f;

    // prologue: stages 0..2
#pragma unroll
    for (int s = 0; s < STAGES - 1; ++s) {
        issue_stage(sbase, s, A, W, m0, n0, s * BK, tid);
        CP_COMMIT();
    }

    for (int kt = 0; kt < NK; ++kt) {
        CP_WAIT2();
        __syncthreads();

        // issue next stage (overlaps with compute below)
        const int knext = kt + STAGES - 1;
        if (knext < NK)
            issue_stage(sbase, knext & (STAGES - 1), A, W, m0, n0, knext * BK, tid);
        CP_COMMIT();

        const uint32_t sA = sbase + (kt & (STAGES - 1)) * STAGE_BYTES;
        const uint32_t sB = sA + 16384;

#pragma unroll
        for (int ks = 0; ks < 4; ++ks) {         // 4 x k16 per BK=64
            uint32_t a[4][4];
#pragma unroll
            for (int im = 0; im < 4; ++im) {
                const int row = warp_m * 64 + im * 16 + lrow;
                const int ch  = ks * 2 + lhalf;
                LDSM_X4(a[im], sA + row * 128 + ((ch ^ (row & 7)) << 4));
            }
            uint32_t b[2][4];
#pragma unroll
            for (int jb = 0; jb < 2; ++jb) {
                const int row = warp_n * 32 + jb * 16 + lrow;
                const int ch  = ks * 2 + lhalf;
                LDSM_X4(b[jb], sB + row * 128 + ((ch ^ (row & 7)) << 4));
            }
#pragma unroll
            for (int im = 0; im < 4; ++im)
#pragma unroll
                for (int jn = 0; jn < 4; ++jn)
                    MMA16816(acc[im][jn], a[im],
                             b[jn >> 1][jn & 1], b[jn >> 1][(jn & 1) + 2]);
        }
        __syncthreads();
    }

    // epilogue: write accumulators
#pragma unroll
    for (int im = 0; im < 4; ++im) {
        const int r0 = m0 + warp_m * 64 + im * 16 + (lane >> 2);
#pragma unroll
        for (int jn = 0; jn < 4; ++jn) {
            const int col = n0 + warp_n * 32 + jn * 8 + (lane & 3) * 2;
            float2 v0 = make_float2(acc[im][jn][0], acc[im][jn][1]);
            float2 v1 = make_float2(acc[im][jn][2], acc[im][jn][3]);
            *(float2*)&out[(size_t)r0 * N_DIM + col]       = v0;
            *(float2*)&out[(size_t)(r0 + 8) * N_DIM + col] = v1;
        }
    }
}

// ---------------------------------------------------------------------------
// LayerNorm (+bias) + LSTM elementwise. One block / batch row; warp = gate.
// ---------------------------------------------------------------------------
__device__ __forceinline__ float sigmoidf_(float x) {
    return 1.0f / (1.0f + expf(-x));
}

__global__ __launch_bounds__(128)
void ln_lstm_kernel(const float* __restrict__ gates,  // [B, 4, H] (no bias)
                    const float* __restrict__ c,      // [B, H]
                    const float* __restrict__ bh,     // [4H]
                    const float* __restrict__ gamma,  // [4, H]
                    const float* __restrict__ beta,   // [4, H]
                    float* __restrict__ h_new,
                    float* __restrict__ c_new) {
    const int b    = blockIdx.x;
    const int wid  = threadIdx.x >> 5;
    const int lane = threadIdx.x & 31;

    __shared__ float sh[4][H_DIM];

    const float* row  = gates + (size_t)b * N_DIM + wid * H_DIM;
    const float* brow = bh + wid * H_DIM;

    float4 v[8];
    float sum = 0.0f, sumsq = 0.0f;
#pragma unroll
    for (int i = 0; i < 8; ++i) {
        const int j = (lane + 32 * i) * 4;
        float4 g  = *(const float4*)&row[j];
        float4 bb = *(const float4*)&brow[j];
        v[i].x = g.x + bb.x; v[i].y = g.y + bb.y;
        v[i].z = g.z + bb.z; v[i].w = g.w + bb.w;
        sum   += v[i].x + v[i].y + v[i].z + v[i].w;
        sumsq += v[i].x * v[i].x + v[i].y * v[i].y
               + v[i].z * v[i].z + v[i].w * v[i].w;
    }
#pragma unroll
    for (int off = 16; off > 0; off >>= 1) {
        sum   += __shfl_xor_sync(0xffffffffu, sum,   off);
        sumsq += __shfl_xor_sync(0xffffffffu, sumsq, off);
    }
    const float inv_n = 1.0f / (float)H_DIM;
    const float mean = sum * inv_n;
    const float var  = fmaxf(sumsq * inv_n - mean * mean, 0.0f);
    const float rstd = rsqrtf(var + 1e-5f);

    const float* gam = gamma + wid * H_DIM;
    const float* bet = beta  + wid * H_DIM;
#pragma unroll
    for (int i = 0; i < 8; ++i) {
        const int j = (lane + 32 * i) * 4;
        float4 gv = *(const float4*)&gam[j];
        float4 bv = *(const float4*)&bet[j];
        float4 y;
        y.x = (v[i].x - mean) * rstd * gv.x + bv.x;
        y.y = (v[i].y - mean) * rstd * gv.y + bv.y;
        y.z = (v[i].z - mean) * rstd * gv.z + bv.z;
        y.w = (v[i].w - mean) * rstd * gv.w + bv.w;
        *(float4*)&sh[wid][j] = y;
    }
    __syncthreads();

    const size_t base = (size_t)b * H_DIM;
#pragma unroll
    for (int ii = 0; ii < 2; ++ii) {
        const int j = (threadIdx.x + 128 * ii) * 4;
        float4 ig = *(const float4*)&sh[0][j];
        float4 fg = *(const float4*)&sh[1][j];
        float4 gg = *(const float4*)&sh[2][j];
        float4 og = *(const float4*)&sh[3][j];
        float4 cv = *(const float4*)&c[base + j];

        float4 cn, hn;
        cn.x = sigmoidf_(fg.x) * cv.x + sigmoidf_(ig.x) * tanhf(gg.x);
        cn.y = sigmoidf_(fg.y) * cv.y + sigmoidf_(ig.y) * tanhf(gg.y);
        cn.z = sigmoidf_(fg.z) * cv.z + sigmoidf_(ig.z) * tanhf(gg.z);
        cn.w = sigmoidf_(fg.w) * cv.w + sigmoidf_(ig.w) * tanhf(gg.w);
        hn.x = sigmoidf_(og.x) * tanhf(cn.x);
        hn.y = sigmoidf_(og.y) * tanhf(cn.y);
        hn.z = sigmoidf_(og.z) * tanhf(cn.z);
        hn.w = sigmoidf_(og.w) * tanhf(cn.w);

        *(float4*)&c_new[base + j] = cn;
        *(float4*)&h_new[base + j] = hn;
    }
}

// ---------------------------------------------------------------------------
// Host launcher
// ---------------------------------------------------------------------------
extern "C" void kernel_launch(void* const* d_in, const int* in_sizes, int n_in,
                              void* d_out, int out_size) {
    const float* x     = (const float*)d_in[0];
    const float* h     = (const float*)d_in[1];
    const float* c     = (const float*)d_in[2];
    const float* Wi    = (const float*)d_in[3];
    const float* Wh    = (const float*)d_in[4];
    const float* bh    = (const float*)d_in[5];
    const float* gamma = (const float*)d_in[6];
    const float* beta  = (const float*)d_in[7];

    float* out   = (float*)d_out;
    float* h_new = out;
    float* c_new = out + (size_t)B_DIM * H_DIM;

    float* gates;         cudaGetSymbolAddress((void**)&gates, g_gates);
    __nv_bfloat16* a_ptr; cudaGetSymbolAddress((void**)&a_ptr, g_Acat);
    __nv_bfloat16* w_ptr; cudaGetSymbolAddress((void**)&w_ptr, g_Wcat);

    pack_a_kernel<<<dim3(K_RAW / 256, B_DIM), 256>>>(x, h);
    pack_w_kernel<<<dim3(K_RAW / 32, N_DIM / 32), dim3(32, 8)>>>(Wi, Wh);

    cudaFuncSetAttribute(gemm_mma_kernel,
                         cudaFuncAttributeMaxDynamicSharedMemorySize, SMEM_BYTES);
    gemm_mma_kernel<<<dim3(N_DIM / TILE_N, B_DIM / TILE_M), 256, SMEM_BYTES>>>(
        a_ptr, w_ptr, gates);

    ln_lstm_kernel<<<B_DIM, 128>>>(gates, c, bh, gamma, beta, h_new, c_new);
}